// round 5
// baseline (speedup 1.0000x reference)
#include <cuda_runtime.h>
#include <cooperative_groups.h>
#include <cstdint>
namespace cg = cooperative_groups;

// Problem constants
#define BATCH  8
#define NPTS   32768
#define NSAMP  8192
#define FEATC  256
#define CSIZE  8                 // cluster size (CTAs per batch)
#define TPB    512
#define PPC    (NPTS / CSIZE)    // 4096 points per CTA
#define PPT    (PPC / TPB)       // 8 points per thread
#define NWARP  (TPB / 32)        // 16

// Sampled indices, produced by fps_kernel, consumed by gather_kernel.
__device__ int g_idx[BATCH * NSAMP];

// ---------------------------------------------------------------------------
// mbarrier helpers. The R3 bug: remote arrive without explicit semantics
// defaults to cta-scope release, which does NOT order the producer's DSMEM
// stores for a remote consumer. Fixed: .release.cluster / .acquire.cluster.
// ---------------------------------------------------------------------------
__device__ __forceinline__ uint32_t smem_u32(const void* p) {
    return (uint32_t)__cvta_generic_to_shared(p);
}
__device__ __forceinline__ void mbar_init(uint32_t a, uint32_t cnt) {
    asm volatile("mbarrier.init.shared.b64 [%0], %1;" :: "r"(a), "r"(cnt) : "memory");
}
// Arrive (release at CLUSTER scope) on the mbarrier at the same smem offset
// in cluster CTA `rank`. Orders our prior DSMEM stores before the arrival.
__device__ __forceinline__ void mbar_arrive_remote(uint32_t local_a, uint32_t rank) {
    asm volatile(
        "{\n\t.reg .b32 ra;\n\t"
        "mapa.shared::cluster.u32 ra, %0, %1;\n\t"
        "mbarrier.arrive.release.cluster.shared::cluster.b64 _, [ra];\n\t}"
        :: "r"(local_a), "r"(rank) : "memory");
}
// Wait with CLUSTER-scope acquire (must observe remote CTAs' DSMEM stores).
__device__ __forceinline__ void mbar_wait_cluster(uint32_t a, uint32_t parity) {
    asm volatile(
        "{\n\t.reg .pred P;\n\t"
        "W%=:\n\t"
        "mbarrier.try_wait.parity.acquire.cluster.shared::cta.b64 P, [%0], %1, 0x989680;\n\t"
        "@!P bra W%=;\n\t}"
        :: "r"(a), "r"(parity) : "memory");
}

// ---------------------------------------------------------------------------
// FPS kernel: one 8-CTA cluster per batch. Per iteration:
//   compute + per-thread argmax (coords carried via select)
//   -> warp argmax via REDUX (max of value bits, then min index among matches)
//   -> __syncthreads -> warp0 REDUX over the 16 warp winners
//   -> warp0 lanes 0..7 write the CTA candidate into rank r's double-buffered
//      DSMEM slot, then remote-arrive (release.cluster) on rank r's mbarrier
//   -> all threads wait the local mbarrier (acquire.cluster)
//   -> per-warp REDUX combine over the 8 slots -> global winner + coords.
//
// Protocol safety (double buffer, count = CSIZE per mbarrier): a producer's
// publish at iteration k+2 (buffer b) requires it passed its local wait at
// k+1, which required every CTA's arrival at k+1, which happens only after
// that CTA's syncthreads(k+1), which is after all its threads finished
// reading buffer b at k. So overwrites are safe and each mbarrier is at most
// one phase in flight.
//
// Tie-break everywhere: max value, then MIN global index (= jnp.argmax
// first-occurrence; indices globally unique so matches are one-hot).
// Distance formula replicates XLA/NVPTX fp contraction exactly (bit-exact
// in R2/R4):  d = fma(dz, dz, fma(dx, dx, dy*dy))
// ---------------------------------------------------------------------------
__global__ void __cluster_dims__(CSIZE, 1, 1) __launch_bounds__(TPB, 1)
fps_kernel(const float* __restrict__ xyz)
{
    cg::cluster_group cluster = cg::this_cluster();
    const int rank  = cluster.block_rank();
    const int batch = blockIdx.x / CSIZE;
    const int tid   = threadIdx.x;
    const int lane  = tid & 31;
    const int wid   = tid >> 5;

    const float* __restrict__ xb = xyz + (size_t)batch * NPTS * 3;

    __shared__ alignas(16) float    s_warp[NWARP][8];      // per-warp winners
    __shared__ alignas(16) float    s_slot[2][CSIZE][8];   // cluster candidates
    __shared__ alignas(8)  uint64_t s_mbar[2];

    if (tid == 0) {
        mbar_init(smem_u32(&s_mbar[0]), CSIZE);
        mbar_init(smem_u32(&s_mbar[1]), CSIZE);
    }
    cluster.sync();   // mbarrier init visible cluster-wide before any arrive

    const uint32_t mbar0 = smem_u32(&s_mbar[0]);
    const int base = rank * PPC + tid;

    // Register-resident point coords and running min distances.
    float px[PPT], py[PPT], pz[PPT], md[PPT];
#pragma unroll
    for (int j = 0; j < PPT; j++) {
        const int p = base + j * TPB;
        px[j] = xb[3 * p + 0];
        py[j] = xb[3 * p + 1];
        pz[j] = xb[3 * p + 2];
        md[j] = 1e10f;            // BIG from the reference
    }

    // First sampled point is index 0 (deterministic variant).
    float cx = xb[0], cy = xb[1], cz = xb[2];
    if (rank == 0 && tid == 0) g_idx[batch * NSAMP] = 0;

    uint32_t ph0 = 0, ph1 = 0;    // per-buffer wait parities

    for (int k = 1; k < NSAMP; k++) {
        // --- per-thread: update min_dist, local argmax (value, index, coords) ---
        float bv, bx, by, bz;
        int   bi;
#pragma unroll
        for (int j = 0; j < PPT; j++) {
            const float dx = __fsub_rn(px[j], cx);
            const float dy = __fsub_rn(py[j], cy);
            const float dz = __fsub_rn(pz[j], cz);
            const float d  = __fmaf_rn(dz, dz,
                              __fmaf_rn(dx, dx, __fmul_rn(dy, dy)));
            const float m  = fminf(md[j], d);
            md[j] = m;
            if (j == 0) {
                bv = m; bi = base; bx = px[0]; by = py[0]; bz = pz[0];
            } else if (m > bv) {   // strict >: earlier (lower) index wins ties
                bv = m; bi = base + j * TPB; bx = px[j]; by = py[j]; bz = pz[j];
            }
        }

        // --- warp argmax via REDUX ---
        const uint32_t uv = __float_as_uint(bv);            // bv >= 0
        const uint32_t kv = __reduce_max_sync(0xffffffffu, uv);
        const uint32_t cand = (uv == kv) ? (uint32_t)bi : 0xffffffffu;
        const uint32_t ki = __reduce_min_sync(0xffffffffu, cand);
        if ((uint32_t)bi == ki) {                           // unique winner lane
            *(float4*)&s_warp[wid][0] =
                make_float4(__uint_as_float(kv), __uint_as_float(ki), bx, by);
            s_warp[wid][4] = bz;
        }
        __syncthreads();

        const int b = k & 1;

        // --- warp0: block argmax over 16 warp winners, fan out to all ranks ---
        if (wid == 0) {
            float sv = 0.f, sx = 0.f, sy = 0.f, sz = 0.f;
            uint32_t si = 0xffffffffu;
            if (lane < NWARP) {
                const float4 t = *(const float4*)&s_warp[lane][0];
                sv = t.x; si = __float_as_uint(t.y); sx = t.z; sy = t.w;
                sz = s_warp[lane][4];
            }
            const uint32_t uv2 = __float_as_uint(sv);
            const uint32_t kv2 = __reduce_max_sync(0xffffffffu, uv2);
            const uint32_t c2  = (uv2 == kv2) ? si : 0xffffffffu;
            const uint32_t ki2 = __reduce_min_sync(0xffffffffu, c2);
            const uint32_t m2  = __ballot_sync(0xffffffffu, c2 == ki2); // one-hot
            const int src = __ffs(m2) - 1;
            const float wx = __shfl_sync(0xffffffffu, sx, src);
            const float wy = __shfl_sync(0xffffffffu, sy, src);
            const float wz = __shfl_sync(0xffffffffu, sz, src);
            if (lane < CSIZE) {
                // lane r writes this CTA's candidate into rank r's slot row,
                // then release-arrives on rank r's mbarrier.
                float* dst = (float*)cluster.map_shared_rank(
                    (void*)&s_slot[b][rank][0], lane);
                *(float4*)dst =
                    make_float4(__uint_as_float(kv2), __uint_as_float(ki2), wx, wy);
                dst[4] = wz;
                mbar_arrive_remote(mbar0 + b * 8, lane);
            }
        }

        // --- wait for all CSIZE candidates (cluster-scope acquire) ---
        mbar_wait_cluster(mbar0 + b * 8, b ? ph1 : ph0);
        if (b) ph1 ^= 1; else ph0 ^= 1;

        // --- per-warp REDUX combine over the CSIZE slots ---
        float sv = 0.f, sx = 0.f, sy = 0.f, sz = 0.f;
        uint32_t si = 0xffffffffu;
        if (lane < CSIZE) {
            const float4 t = *(const float4*)&s_slot[b][lane][0];
            sv = t.x; si = __float_as_uint(t.y); sx = t.z; sy = t.w;
            sz = s_slot[b][lane][4];
        }
        const uint32_t uv3 = __float_as_uint(sv);
        const uint32_t kv3 = __reduce_max_sync(0xffffffffu, uv3);
        const uint32_t c3  = (uv3 == kv3) ? si : 0xffffffffu;
        const uint32_t ki3 = __reduce_min_sync(0xffffffffu, c3);
        const uint32_t m3  = __ballot_sync(0xffffffffu, c3 == ki3);    // one-hot
        const int src3 = __ffs(m3) - 1;
        cx = __shfl_sync(0xffffffffu, sx, src3);
        cy = __shfl_sync(0xffffffffu, sy, src3);
        cz = __shfl_sync(0xffffffffu, sz, src3);

        if (rank == 0 && tid == 0) g_idx[batch * NSAMP + k] = (int)ki3;
    }
}

// ---------------------------------------------------------------------------
// Gather kernel: one block per sampled row. 256 feature floats (64 x float4)
// plus the 3 xyz floats. Output: [xyz (B,S,3)] then [feature (B,S,256)].
// ---------------------------------------------------------------------------
__global__ void __launch_bounds__(64)
gather_kernel(const float* __restrict__ xyz, const float* __restrict__ feat,
              float* __restrict__ out)
{
    const int row = blockIdx.x;          // 0 .. BATCH*NSAMP-1
    const int b = row / NSAMP;
    const int p = g_idx[row];

    float* out_xyz  = out;
    float* out_feat = out + (size_t)BATCH * NSAMP * 3;

    const float4* src = (const float4*)(feat + ((size_t)b * NPTS + p) * FEATC);
    float4*       dst = (float4*)(out_feat + (size_t)row * FEATC);
    dst[threadIdx.x] = src[threadIdx.x];

    if (threadIdx.x < 3) {
        out_xyz[(size_t)row * 3 + threadIdx.x] =
            xyz[((size_t)b * NPTS + p) * 3 + threadIdx.x];
    }
}

extern "C" void kernel_launch(void* const* d_in, const int* in_sizes, int n_in,
                              void* d_out, int out_size)
{
    const float* xyz  = (const float*)d_in[0];
    const float* feat = (const float*)d_in[1];
    float*       out  = (float*)d_out;

    fps_kernel<<<BATCH * CSIZE, TPB>>>(xyz);
    gather_kernel<<<BATCH * NSAMP, 64>>>(xyz, feat, out);
}